// round 8
// baseline (speedup 1.0000x reference)
#include <cuda_runtime.h>
#include <cuda_bf16.h>
#include <cstdint>
#include <math.h>

typedef __nv_bfloat16 bf16;

// Shapes: T=64, B=64, S=64, E=1024, D=1024, G=4096
// Persistent kernel: 256 CTAs x 512 threads, TWO CTAs per SM (<=64 regs), global barriers.
// GEMM: out[n][b] split-K partials = sum_k W[n][k]*Z[b][k], 3-term hi/lo bf16 mma.sync.
// Attention: scores[b,s] = h1[b] . ctxW[s,b], ctxW precomputed once.

#define NCTA 256

// ---------------- static device scratch ----------------
__device__ __align__(16) bf16 g_W0e_h[4096*1024], g_W0e_l[4096*1024];
__device__ __align__(16) bf16 g_Wc0_h[4096*2048], g_Wc0_l[4096*2048];
__device__ __align__(16) bf16 g_Wc1_h[4096*2048], g_Wc1_l[4096*2048];
__device__ __align__(16) bf16 g_WinT_h[1024*1024], g_WinT_l[1024*1024];  // W_in^T: [e][d]
__device__ __align__(16) bf16 g_Wout_h[1024*2048], g_Wout_l[1024*2048];
__device__ __align__(16) bf16 g_embh[4096*1024],  g_embl[4096*1024];
__device__ __align__(16) bf16 g_ctxRh[4096*1024], g_ctxRl[4096*1024];   // ctx rows per bpair
__device__ __align__(16) float g_ctxWT[64*64*1024];  // [(bpair*16+eblk)][srow(128)][elocal(64)]
__device__ __align__(16) float g_embW[64*4096*64];   // [t][n][b]
__device__ __align__(16) float g_part[8*4096*64];    // 8 slices [4096][64] (= 32 of [1024][64])
__device__ __align__(16) bf16 g_Z0h[64*2048], g_Z0l[64*2048];  // [feed | h0_prev]
__device__ __align__(16) bf16 g_Z1h[64*2048], g_Z1l[64*2048];  // [h0_new | h1_prev]
__device__ __align__(16) bf16 g_Zoh[64*2048], g_Zol[64*2048];  // [cvec | h1_new]
__device__ __align__(16) float g_h1f[64*1024];                 // fp32 h1 [b][d]
__device__ __align__(16) float g_cT0[1024*64], g_cT1[1024*64];
__device__ __align__(16) float g_bias0[4096], g_bias1[4096];
__device__ int g_bar_cnt = 0;
__device__ int g_bar_phase = 0;

// ---------------- PTX helpers ----------------
__device__ __forceinline__ uint32_t smem_u32(const void* p) {
    uint32_t a;
    asm("{ .reg .u64 t; cvta.to.shared.u64 t, %1; cvt.u32.u64 %0, t; }" : "=r"(a) : "l"(p));
    return a;
}
__device__ __forceinline__ void ldm4(uint32_t* r, uint32_t a) {
    asm volatile("ldmatrix.sync.aligned.m8n8.x4.shared.b16 {%0,%1,%2,%3}, [%4];"
                 : "=r"(r[0]), "=r"(r[1]), "=r"(r[2]), "=r"(r[3]) : "r"(a));
}
__device__ __forceinline__ void mma_bf16(float* c, const uint32_t* a, uint32_t b0, uint32_t b1) {
    asm volatile("mma.sync.aligned.m16n8k16.row.col.f32.bf16.bf16.f32 "
                 "{%0,%1,%2,%3}, {%4,%5,%6,%7}, {%8,%9}, {%0,%1,%2,%3};"
                 : "+f"(c[0]), "+f"(c[1]), "+f"(c[2]), "+f"(c[3])
                 : "r"(a[0]), "r"(a[1]), "r"(a[2]), "r"(a[3]), "r"(b0), "r"(b1));
}
__device__ __forceinline__ void cpa16(uint32_t s, const void* g) {
    asm volatile("cp.async.cg.shared.global [%0], [%1], 16;" :: "r"(s), "l"(g));
}
#define CP_COMMIT() asm volatile("cp.async.commit_group;" ::: "memory")

__device__ __forceinline__ void hilo(float x, bf16& h, bf16& l) {
    h = __float2bfloat16(x);
    l = __float2bfloat16(x - __bfloat162float(h));
}

// global counter barrier; all NCTA CTAs co-resident (2 CTA/SM by smem+regs)
__device__ __forceinline__ void gsync(int& tgt) {
    __syncthreads();
    tgt++;
    if (threadIdx.x == 0) {
        __threadfence();
        if (atomicAdd(&g_bar_cnt, 1) == NCTA - 1) {
            atomicExch(&g_bar_cnt, 0);
            __threadfence();
            atomicAdd(&g_bar_phase, 1);
        } else {
            while (*(volatile int*)&g_bar_phase - tgt < 0) {}
            __threadfence();
        }
    }
    __syncthreads();
}

// ---------------- GEMM tile (device fn; 512 threads, 4x4 warp grid) ----------------
static constexpr int PITCH = 72;
static constexpr int WBYTES = 128 * PITCH * 2;
static constexpr int ZBYTES = 64 * PITCH * 2;
static constexpr int BUFBYTES = 2 * WBYTES + 2 * ZBYTES;  // 55296
static constexpr int GEMM_SMEM = 2 * BUFBYTES;            // 110592

__device__ __forceinline__ void gemm_tile(
    const bf16* __restrict__ Wh, const bf16* __restrict__ Wl,
    const bf16* __restrict__ Zh, const bf16* __restrict__ Zl,
    int ldz, float* __restrict__ out, int K,
    int n0, int k0, int chunks, char* dsm)
{
    const int tid  = threadIdx.x;
    const int lane = tid & 31, wid = tid >> 5;
    const int wm = wid >> 2, wn = wid & 3;
    const uint32_t sb = smem_u32(dsm);

    float acc[2][2][4];
#pragma unroll
    for (int mi = 0; mi < 2; mi++)
#pragma unroll
        for (int nj = 0; nj < 2; nj++)
#pragma unroll
            for (int q = 0; q < 4; q++) acc[mi][nj][q] = 0.f;

    auto stage = [&](int c) {
        const uint32_t S = sb + (c & 1) * BUFBYTES;
        const int kb = k0 + c * 64;
#pragma unroll
        for (int i = 0; i < 2; i++) {
            int idx = i * 512 + tid;
            int row = idx >> 3, cg = idx & 7;
            size_t g = (size_t)(n0 + row) * K + kb + cg * 8;
            uint32_t d = S + (row * PITCH + cg * 8) * 2;
            cpa16(d, Wh + g);
            cpa16(d + WBYTES, Wl + g);
        }
        {
            int row = tid >> 3, cg = tid & 7;
            size_t g = (size_t)row * ldz + kb + cg * 8;
            uint32_t d = S + 2 * WBYTES + (row * PITCH + cg * 8) * 2;
            cpa16(d, Zh + g);
            cpa16(d + ZBYTES, Zl + g);
        }
        CP_COMMIT();
    };

    stage(0);
    for (int c = 0; c < chunks; c++) {
        if (c + 1 < chunks) {
            stage(c + 1);
            asm volatile("cp.async.wait_group 1;" ::: "memory");
        } else {
            asm volatile("cp.async.wait_group 0;" ::: "memory");
        }
        __syncthreads();

        const uint32_t S = sb + (c & 1) * BUFBYTES;
        const uint32_t aw = S + ((wm * 32 + (lane & 15)) * PITCH + (lane >> 4) * 8) * 2;
        const uint32_t bz = S + 2 * WBYTES + ((wn * 16 + (lane & 15)) * PITCH + (lane >> 4) * 8) * 2;

#pragma unroll
        for (int ks = 0; ks < 4; ks++) {
            const uint32_t koff = ks * 32;
            uint32_t ah[2][4], al[2][4], bh[4], bl[4];
#pragma unroll
            for (int mi = 0; mi < 2; mi++) {
                uint32_t a = aw + mi * 16 * PITCH * 2 + koff;
                ldm4(ah[mi], a);
                ldm4(al[mi], a + WBYTES);
            }
            ldm4(bh, bz + koff);
            ldm4(bl, bz + koff + ZBYTES);
#pragma unroll
            for (int mi = 0; mi < 2; mi++)
#pragma unroll
                for (int nj = 0; nj < 2; nj++) {
                    mma_bf16(acc[mi][nj], ah[mi], bh[nj], bh[2 + nj]);
                    mma_bf16(acc[mi][nj], ah[mi], bl[nj], bl[2 + nj]);
                    mma_bf16(acc[mi][nj], al[mi], bh[nj], bh[2 + nj]);
                }
        }
        __syncthreads();
    }

#pragma unroll
    for (int mi = 0; mi < 2; mi++)
#pragma unroll
        for (int nj = 0; nj < 2; nj++) {
            int m = n0 + wm * 32 + mi * 16 + (lane >> 2);
            int b = wn * 16 + nj * 8 + (lane & 3) * 2;
            *(float2*)(out + (size_t)m * 64 + b) =
                make_float2(acc[mi][nj][0], acc[mi][nj][1]);
            *(float2*)(out + (size_t)(m + 8) * 64 + b) =
                make_float2(acc[mi][nj][2], acc[mi][nj][3]);
        }
}

// ---------------- cell phase (one element per thread; 128 CTAs) ----------------
__device__ __forceinline__ void cell_phase(
    int e, const float* __restrict__ part,
    const float* __restrict__ base, const float* __restrict__ bias,
    float* __restrict__ cT,
    bf16* hAh, bf16* hAl, int offA, bf16* hBh, bf16* hBl, int offB,
    float* __restrict__ h1f)
{
    int d = e >> 6, b = e & 63;
    float g[4];
#pragma unroll
    for (int j = 0; j < 4; j++) {
        float acc = bias[j * 1024 + d];
        if (base) acc += base[(size_t)j * 65536 + e];
#pragma unroll
        for (int ks = 0; ks < 8; ks++)
            acc += part[(size_t)ks * 262144 + (size_t)j * 65536 + e];
        g[j] = acc;
    }
    float ig = 1.f / (1.f + expf(-g[0]));
    float fg = 1.f / (1.f + expf(-g[1]));
    float gg = tanhf(g[2]);
    float og = 1.f / (1.f + expf(-g[3]));
    float cn = fg * cT[e] + ig * gg;
    float h  = og * tanhf(cn);
    cT[e] = cn;
    bf16 hh, hl;
    hilo(h, hh, hl);
    hAh[b * 2048 + offA + d] = hh; hAl[b * 2048 + offA + d] = hl;
    hBh[b * 2048 + offB + d] = hh; hBl[b * 2048 + offB + d] = hl;
    if (h1f) h1f[b * 1024 + d] = h;
}

// ---------------- persistent kernel (2 CTAs/SM) ----------------
__global__ void __launch_bounds__(512, 2) persistent_k(
    const float* __restrict__ ctx, float* __restrict__ outs, float* __restrict__ attns)
{
    extern __shared__ __align__(16) char dsm[];
    const int bi = blockIdx.x, tid = threadIdx.x;
    const int lane = tid & 31, w = tid >> 5;
    int tgt = *(volatile int*)&g_bar_phase;

    for (int t = 0; t < 64; t++) {
        // ---- P1: LSTM0 GEMM: mtile=bi>>3 (32), ks=bi&7 (8), Kchunk=256 ----
        gemm_tile(g_Wc0_h, g_Wc0_l, g_Z0h, g_Z0l, 2048,
                  g_part + (size_t)(bi & 7) * 262144, 2048,
                  (bi >> 3) * 128, (bi & 7) * 256, 4, dsm);
        gsync(tgt);
        // ---- P2: cell0 (CTAs 0-127) ----
        if (bi < 128)
            cell_phase(bi * 512 + tid, g_part, g_embW + (size_t)t * 262144, g_bias0,
                       g_cT0, g_Z1h, g_Z1l, 0, g_Z0h, g_Z0l, 1024, nullptr);
        gsync(tgt);
        // ---- P3: LSTM1 GEMM ----
        gemm_tile(g_Wc1_h, g_Wc1_l, g_Z1h, g_Z1l, 2048,
                  g_part + (size_t)(bi & 7) * 262144, 2048,
                  (bi >> 3) * 128, (bi & 7) * 256, 4, dsm);
        gsync(tgt);
        // ---- P4: cell1 (CTAs 0-127; also emits fp32 h1) ----
        if (bi < 128)
            cell_phase(bi * 512 + tid, g_part, nullptr, g_bias1,
                       g_cT1, g_Zoh, g_Zol, 1024, g_Z1h, g_Z1l, 1024, g_h1f);
        gsync(tgt);
        // ---- P5: CTAs 0-63 attention; CTAs 64-191 out-GEMM h1 half (16 ks) ----
        if (bi < 64) {
            const int b = bi;
            float* qs = (float*)dsm;          // 1024 fp32 h1[b]
            float* sc = qs + 1024;            // 64 scores
            for (int d = tid; d < 1024; d += 512) qs[d] = g_h1f[b * 1024 + d];
            __syncthreads();
            const int bpair = b >> 1, brow = (b & 1) * 64;
#pragma unroll
            for (int so = 0; so < 4; so++) {
                int s = w * 4 + so;
                float acc = 0.f;
#pragma unroll
                for (int eblk = 0; eblk < 16; eblk++) {
                    const float* cwp = g_ctxWT +
                        ((size_t)(bpair * 16 + eblk) * 128 + brow + s) * 64;
                    acc += qs[eblk * 64 + lane] * cwp[lane];
                    acc += qs[eblk * 64 + 32 + lane] * cwp[32 + lane];
                }
#pragma unroll
                for (int off = 16; off; off >>= 1)
                    acc += __shfl_down_sync(0xffffffffu, acc, off);
                if (lane == 0) sc[s] = acc;
            }
            __syncthreads();
            if (tid < 32) {
                float v0 = sc[tid], v1 = sc[tid + 32];
                float m = fmaxf(v0, v1);
#pragma unroll
                for (int off = 16; off; off >>= 1)
                    m = fmaxf(m, __shfl_xor_sync(0xffffffffu, m, off));
                float e0 = expf(v0 - m), e1 = expf(v1 - m);
                float s = e0 + e1;
#pragma unroll
                for (int off = 16; off; off >>= 1)
                    s += __shfl_xor_sync(0xffffffffu, s, off);
                float inv = 1.f / s;
                float a0 = e0 * inv, a1 = e1 * inv;
                sc[tid] = a0; sc[tid + 32] = a1;
                float* at = attns + (size_t)t * 4096 + b * 64;
                at[tid] = a0; at[tid + 32] = a1;
            }
            __syncthreads();
            for (int d = tid; d < 1024; d += 512) {
                float acc = 0.f;
#pragma unroll 8
                for (int s = 0; s < 64; s++)
                    acc += sc[s] * ctx[((size_t)s * 64 + b) * 1024 + d];
                bf16 hh, hl;
                hilo(acc, hh, hl);
                g_Zoh[b * 2048 + d] = hh;
                g_Zol[b * 2048 + d] = hl;
            }
        } else if (bi < 192) {
            const int idx = bi - 64;                  // 0..127
            const int mt = idx >> 4, ks = idx & 15;   // 8 mtiles x 16 ksplits
            gemm_tile(g_Wout_h, g_Wout_l, g_Zoh, g_Zol, 2048,
                      g_part + (size_t)(16 + ks) * 65536, 2048,
                      mt * 128, 1024 + ks * 64, 1, dsm);
        }
        gsync(tgt);
        // ---- P6: out GEMM cvec half (CTAs 0-127): mtile=bi>>4, ks=bi&15, 1 chunk ----
        if (bi < 128)
            gemm_tile(g_Wout_h, g_Wout_l, g_Zoh, g_Zol, 2048,
                      g_part + (size_t)(bi & 15) * 65536, 2048,
                      (bi >> 4) * 128, (bi & 15) * 64, 1, dsm);
        gsync(tgt);
        // ---- P7: reduce 32 slices + tanh + outputs + next input feed (CTAs 0-127) ----
        if (bi < 128) {
            int e = bi * 512 + tid;
            int d = e >> 6, b = e & 63;
            float acc = 0.f;
#pragma unroll
            for (int ks = 0; ks < 32; ks++)
                acc += g_part[(size_t)ks * 65536 + e];
            float h = tanhf(acc);
            outs[(size_t)t * 65536 + b * 1024 + d] = h;
            bf16 hh, hl;
            hilo(h, hh, hl);
            g_Z0h[b * 2048 + d] = hh;
            g_Z0l[b * 2048 + d] = hl;
        }
        gsync(tgt);
    }
}

// ---------------- embW precompute GEMM (standalone, 2048 CTAs) ----------------
__global__ void __launch_bounds__(512, 2) gemm_pre(float* __restrict__ out)
{
    extern __shared__ __align__(16) char dsm[];
    gemm_tile(g_W0e_h, g_W0e_l,
              g_embh + (size_t)blockIdx.y * 65536, g_embl + (size_t)blockIdx.y * 65536,
              1024, out + (size_t)blockIdx.y * 262144, 1024,
              blockIdx.x * 128, 0, 16, dsm);
}

// ---------------- ctxW precompute ----------------
__global__ void __launch_bounds__(512, 2) ctxw_pre(float* __restrict__ out)
{
    extern __shared__ __align__(16) char dsm[];
    const int bpair = blockIdx.x;   // 32
    const int eblk  = blockIdx.y;   // 16
    gemm_tile(g_ctxRh + (size_t)bpair * 131072, g_ctxRl + (size_t)bpair * 131072,
              g_WinT_h + (size_t)eblk * 65536, g_WinT_l + (size_t)eblk * 65536,
              1024, out + ((size_t)bpair * 16 + eblk) * 8192, 1024,
              0, 0, 16, dsm);
}

// ---------------- init state ----------------
__global__ void init_state(const float* __restrict__ input_feed,
                           const float* __restrict__ h0, const float* __restrict__ c0)
{
    int e = blockIdx.x * blockDim.x + threadIdx.x;  // 65536
    int b = e >> 10, d = e & 1023;
    bf16 hh, hl;
    hilo(input_feed[e], hh, hl);
    g_Z0h[b * 2048 + d] = hh; g_Z0l[b * 2048 + d] = hl;
    hilo(h0[e], hh, hl);
    g_Z0h[b * 2048 + 1024 + d] = hh; g_Z0l[b * 2048 + 1024 + d] = hl;
    hilo(h0[65536 + e], hh, hl);
    g_Z1h[b * 2048 + 1024 + d] = hh; g_Z1l[b * 2048 + 1024 + d] = hl;
    g_cT0[d * 64 + b] = c0[e];
    g_cT1[d * 64 + b] = c0[65536 + e];
}

// ---------------- weight prep ----------------
__global__ void prep_w(const float* __restrict__ W_ih0, const float* __restrict__ W_hh0,
                       const float* __restrict__ W_ih1, const float* __restrict__ W_hh1,
                       const float* __restrict__ W_in,  const float* __restrict__ W_out,
                       const float* __restrict__ emb,   const float* __restrict__ ctx,
                       const float* __restrict__ b_ih0, const float* __restrict__ b_hh0,
                       const float* __restrict__ b_ih1, const float* __restrict__ b_hh1)
{
    size_t stride = (size_t)gridDim.x * blockDim.x;
    for (size_t i = (size_t)blockIdx.x * blockDim.x + threadIdx.x;
         i < 4096ull * 2048ull; i += stride) {
        size_t n = i >> 11, k = i & 2047;
        float v0 = (k < 1024) ? W_ih0[n * 2048 + 1024 + k] : W_hh0[n * 1024 + (k - 1024)];
        hilo(v0, g_Wc0_h[i], g_Wc0_l[i]);
        float v1 = (k < 1024) ? W_ih1[n * 1024 + k] : W_hh1[n * 1024 + (k - 1024)];
        hilo(v1, g_Wc1_h[i], g_Wc1_l[i]);
        if (n < 1024) hilo(W_out[i], g_Wout_h[i], g_Wout_l[i]);
        if (i < 4096ull * 1024ull) {
            size_t nn = i >> 10, kk = i & 1023;
            hilo(W_ih0[nn * 2048 + kk], g_W0e_h[i], g_W0e_l[i]);
            hilo(emb[i], g_embh[i], g_embl[i]);
            size_t b = (i >> 10) & 63, s = i >> 16, d = i & 1023;
            size_t ri = ((b >> 1) * 128 + (b & 1) * 64 + s) * 1024 + d;
            hilo(ctx[i], g_ctxRh[ri], g_ctxRl[ri]);
        }
        if (i < 1024ull * 1024ull) {
            size_t ti = (i & 1023) * 1024 + (i >> 10);
            hilo(W_in[i], g_WinT_h[ti], g_WinT_l[ti]);
        }
        if (i < 4096) {
            g_bias0[i] = b_ih0[i] + b_hh0[i];
            g_bias1[i] = b_ih1[i] + b_hh1[i];
        }
    }
}

// ---------------- host orchestration ----------------
extern "C" void kernel_launch(void* const* d_in, const int* in_sizes, int n_in,
                              void* d_out, int out_size)
{
    (void)in_sizes; (void)n_in; (void)out_size;
    const float* emb        = (const float*)d_in[0];
    const float* context    = (const float*)d_in[1];
    const float* input_feed = (const float*)d_in[2];
    const float* h0         = (const float*)d_in[3];
    const float* c0         = (const float*)d_in[4];
    const float* W_ih0      = (const float*)d_in[5];
    const float* W_hh0      = (const float*)d_in[6];
    const float* b_ih0      = (const float*)d_in[7];
    const float* b_hh0      = (const float*)d_in[8];
    const float* W_ih1      = (const float*)d_in[9];
    const float* W_hh1      = (const float*)d_in[10];
    const float* b_ih1      = (const float*)d_in[11];
    const float* b_hh1      = (const float*)d_in[12];
    const float* W_in       = (const float*)d_in[13];
    const float* W_out      = (const float*)d_in[14];

    float* outs  = (float*)d_out;
    float* attns = outs + 64 * 64 * 1024;

    static bool attr_set = false;
    if (!attr_set) {
        cudaFuncSetAttribute(persistent_k, cudaFuncAttributeMaxDynamicSharedMemorySize, GEMM_SMEM);
        cudaFuncSetAttribute(gemm_pre, cudaFuncAttributeMaxDynamicSharedMemorySize, GEMM_SMEM);
        cudaFuncSetAttribute(ctxw_pre, cudaFuncAttributeMaxDynamicSharedMemorySize, GEMM_SMEM);
        attr_set = true;
    }

    float *pEmbW, *pCtxWT;
    cudaGetSymbolAddress((void**)&pEmbW, g_embW);
    cudaGetSymbolAddress((void**)&pCtxWT, g_ctxWT);

    prep_w<<<4096, 256>>>(W_ih0, W_hh0, W_ih1, W_hh1, W_in, W_out, emb, context,
                          b_ih0, b_hh0, b_ih1, b_hh1);
    init_state<<<256, 256>>>(input_feed, h0, c0);
    ctxw_pre<<<dim3(32, 16), 512, GEMM_SMEM>>>(pCtxWT);
    gemm_pre<<<dim3(32, 64), 512, GEMM_SMEM>>>(pEmbW);
    persistent_k<<<NCTA, 512, GEMM_SMEM>>>(context, outs, attns);
}

// round 9
// speedup vs baseline: 1.4380x; 1.4380x over previous
#include <cuda_runtime.h>
#include <cuda_bf16.h>
#include <cstdint>
#include <math.h>

typedef __nv_bfloat16 bf16;

// Shapes: T=64, B=64, S=64, E=1024, D=1024, G=4096
// Persistent kernel: 128 CTAs x 512 threads, one CTA per SM, global barriers.
// GEMM: out[n][b] split-K partials = sum_k W[n][k]*Z[b][k], 3-term hi/lo bf16 mma.sync.
// Attention: scores[b,s] = h1[b] . ctxW[s,b], ctxW precomputed once.
// R9: streaming accesses (partials, embW, outs) use evict-first (.cs) hints so the
// per-step weight set (~107MB) stays L2-resident instead of thrashing to DRAM.

#define NCTA 128

// ---------------- static device scratch ----------------
__device__ __align__(16) bf16 g_W0e_h[4096*1024], g_W0e_l[4096*1024];
__device__ __align__(16) bf16 g_Wc0_h[4096*2048], g_Wc0_l[4096*2048];
__device__ __align__(16) bf16 g_Wc1_h[4096*2048], g_Wc1_l[4096*2048];
__device__ __align__(16) bf16 g_WinT_h[1024*1024], g_WinT_l[1024*1024];  // W_in^T: [e][d]
__device__ __align__(16) bf16 g_Wout_h[1024*2048], g_Wout_l[1024*2048];
__device__ __align__(16) bf16 g_embh[4096*1024],  g_embl[4096*1024];
__device__ __align__(16) bf16 g_ctxRh[4096*1024], g_ctxRl[4096*1024];   // ctx rows per bpair
__device__ __align__(16) float g_ctxWT[64*64*1024];  // [(bpair*16+eblk)][srow(128)][elocal(64)]
__device__ __align__(16) float g_embW[64*4096*64];   // [t][n][b]
__device__ __align__(16) float g_part[24*1024*64 > 4*4096*64 ? 24*1024*64 : 4*4096*64];
__device__ __align__(16) bf16 g_Z0h[64*2048], g_Z0l[64*2048];  // [feed | h0_prev]
__device__ __align__(16) bf16 g_Z1h[64*2048], g_Z1l[64*2048];  // [h0_new | h1_prev]
__device__ __align__(16) bf16 g_Zoh[64*2048], g_Zol[64*2048];  // [cvec | h1_new]
__device__ __align__(16) float g_h1f[64*1024];                 // fp32 h1 [b][d]
__device__ __align__(16) float g_cT0[1024*64], g_cT1[1024*64];
__device__ __align__(16) float g_bias0[4096], g_bias1[4096];
__device__ int g_bar_cnt = 0;
__device__ int g_bar_phase = 0;

// ---------------- PTX helpers ----------------
__device__ __forceinline__ uint32_t smem_u32(const void* p) {
    uint32_t a;
    asm("{ .reg .u64 t; cvta.to.shared.u64 t, %1; cvt.u32.u64 %0, t; }" : "=r"(a) : "l"(p));
    return a;
}
__device__ __forceinline__ void ldm4(uint32_t* r, uint32_t a) {
    asm volatile("ldmatrix.sync.aligned.m8n8.x4.shared.b16 {%0,%1,%2,%3}, [%4];"
                 : "=r"(r[0]), "=r"(r[1]), "=r"(r[2]), "=r"(r[3]) : "r"(a));
}
__device__ __forceinline__ void mma_bf16(float* c, const uint32_t* a, uint32_t b0, uint32_t b1) {
    asm volatile("mma.sync.aligned.m16n8k16.row.col.f32.bf16.bf16.f32 "
                 "{%0,%1,%2,%3}, {%4,%5,%6,%7}, {%8,%9}, {%0,%1,%2,%3};"
                 : "+f"(c[0]), "+f"(c[1]), "+f"(c[2]), "+f"(c[3])
                 : "r"(a[0]), "r"(a[1]), "r"(a[2]), "r"(a[3]), "r"(b0), "r"(b1));
}
__device__ __forceinline__ void cpa16(uint32_t s, const void* g) {
    asm volatile("cp.async.cg.shared.global [%0], [%1], 16;" :: "r"(s), "l"(g));
}
#define CP_COMMIT() asm volatile("cp.async.commit_group;" ::: "memory")

__device__ __forceinline__ void hilo(float x, bf16& h, bf16& l) {
    h = __float2bfloat16(x);
    l = __float2bfloat16(x - __bfloat162float(h));
}

// global counter barrier; all NCTA CTAs co-resident (1 CTA/SM by smem)
__device__ __forceinline__ void gsync(int& tgt) {
    __syncthreads();
    tgt++;
    if (threadIdx.x == 0) {
        __threadfence();
        if (atomicAdd(&g_bar_cnt, 1) == NCTA - 1) {
            atomicExch(&g_bar_cnt, 0);
            __threadfence();
            atomicAdd(&g_bar_phase, 1);
        } else {
            while (*(volatile int*)&g_bar_phase - tgt < 0) {}
            __threadfence();
        }
    }
    __syncthreads();
}

// ---------------- GEMM tile (device fn; 512 threads, 4x4 warp grid) ----------------
static constexpr int PITCH = 72;
static constexpr int WBYTES = 128 * PITCH * 2;
static constexpr int ZBYTES = 64 * PITCH * 2;
static constexpr int BUFBYTES = 2 * WBYTES + 2 * ZBYTES;  // 55296
static constexpr int GEMM_SMEM = 2 * BUFBYTES;            // 110592

__device__ __forceinline__ void gemm_tile(
    const bf16* __restrict__ Wh, const bf16* __restrict__ Wl,
    const bf16* __restrict__ Zh, const bf16* __restrict__ Zl,
    int ldz, float* __restrict__ out, int K,
    int n0, int k0, int chunks, char* dsm)
{
    const int tid  = threadIdx.x;
    const int lane = tid & 31, wid = tid >> 5;
    const int wm = wid >> 2, wn = wid & 3;
    const uint32_t sb = smem_u32(dsm);

    float acc[2][2][4];
#pragma unroll
    for (int mi = 0; mi < 2; mi++)
#pragma unroll
        for (int nj = 0; nj < 2; nj++)
#pragma unroll
            for (int q = 0; q < 4; q++) acc[mi][nj][q] = 0.f;

    auto stage = [&](int c) {
        const uint32_t S = sb + (c & 1) * BUFBYTES;
        const int kb = k0 + c * 64;
#pragma unroll
        for (int i = 0; i < 2; i++) {
            int idx = i * 512 + tid;
            int row = idx >> 3, cg = idx & 7;
            size_t g = (size_t)(n0 + row) * K + kb + cg * 8;
            uint32_t d = S + (row * PITCH + cg * 8) * 2;
            cpa16(d, Wh + g);
            cpa16(d + WBYTES, Wl + g);
        }
        {
            int row = tid >> 3, cg = tid & 7;
            size_t g = (size_t)row * ldz + kb + cg * 8;
            uint32_t d = S + 2 * WBYTES + (row * PITCH + cg * 8) * 2;
            cpa16(d, Zh + g);
            cpa16(d + ZBYTES, Zl + g);
        }
        CP_COMMIT();
    };

    stage(0);
    for (int c = 0; c < chunks; c++) {
        if (c + 1 < chunks) {
            stage(c + 1);
            asm volatile("cp.async.wait_group 1;" ::: "memory");
        } else {
            asm volatile("cp.async.wait_group 0;" ::: "memory");
        }
        __syncthreads();

        const uint32_t S = sb + (c & 1) * BUFBYTES;
        const uint32_t aw = S + ((wm * 32 + (lane & 15)) * PITCH + (lane >> 4) * 8) * 2;
        const uint32_t bz = S + 2 * WBYTES + ((wn * 16 + (lane & 15)) * PITCH + (lane >> 4) * 8) * 2;

#pragma unroll
        for (int ks = 0; ks < 4; ks++) {
            const uint32_t koff = ks * 32;
            uint32_t ah[2][4], al[2][4], bh[4], bl[4];
#pragma unroll
            for (int mi = 0; mi < 2; mi++) {
                uint32_t a = aw + mi * 16 * PITCH * 2 + koff;
                ldm4(ah[mi], a);
                ldm4(al[mi], a + WBYTES);
            }
            ldm4(bh, bz + koff);
            ldm4(bl, bz + koff + ZBYTES);
#pragma unroll
            for (int mi = 0; mi < 2; mi++)
#pragma unroll
                for (int nj = 0; nj < 2; nj++) {
                    mma_bf16(acc[mi][nj], ah[mi], bh[nj], bh[2 + nj]);
                    mma_bf16(acc[mi][nj], ah[mi], bl[nj], bl[2 + nj]);
                    mma_bf16(acc[mi][nj], al[mi], bh[nj], bh[2 + nj]);
                }
        }
        __syncthreads();
    }

    // epilogue: streaming (evict-first) writes — partials/embW are read once
#pragma unroll
    for (int mi = 0; mi < 2; mi++)
#pragma unroll
        for (int nj = 0; nj < 2; nj++) {
            int m = n0 + wm * 32 + mi * 16 + (lane >> 2);
            int b = wn * 16 + nj * 8 + (lane & 3) * 2;
            __stcs((float2*)(out + (size_t)m * 64 + b),
                   make_float2(acc[mi][nj][0], acc[mi][nj][1]));
            __stcs((float2*)(out + (size_t)(m + 8) * 64 + b),
                   make_float2(acc[mi][nj][2], acc[mi][nj][3]));
        }
}

// ---------------- cell phase (one element per thread; 128 CTAs) ----------------
__device__ __forceinline__ void cell_phase(
    int e, const float* __restrict__ part,
    const float* __restrict__ base, const float* __restrict__ bias,
    float* __restrict__ cT,
    bf16* hAh, bf16* hAl, int offA, bf16* hBh, bf16* hBl, int offB,
    float* __restrict__ h1f)
{
    int d = e >> 6, b = e & 63;
    float g[4];
#pragma unroll
    for (int j = 0; j < 4; j++) {
        float acc = bias[j * 1024 + d];
        if (base) acc += __ldcs(base + (size_t)j * 65536 + e);
#pragma unroll
        for (int ks = 0; ks < 4; ks++)
            acc += __ldcs(part + (size_t)ks * 262144 + (size_t)j * 65536 + e);
        g[j] = acc;
    }
    float ig = 1.f / (1.f + expf(-g[0]));
    float fg = 1.f / (1.f + expf(-g[1]));
    float gg = tanhf(g[2]);
    float og = 1.f / (1.f + expf(-g[3]));
    float cn = fg * cT[e] + ig * gg;
    float h  = og * tanhf(cn);
    cT[e] = cn;
    bf16 hh, hl;
    hilo(h, hh, hl);
    hAh[b * 2048 + offA + d] = hh; hAl[b * 2048 + offA + d] = hl;
    hBh[b * 2048 + offB + d] = hh; hBl[b * 2048 + offB + d] = hl;
    if (h1f) h1f[b * 1024 + d] = h;
}

// ---------------- persistent kernel ----------------
__global__ void __launch_bounds__(512) persistent_k(
    const float* __restrict__ ctx, float* __restrict__ outs, float* __restrict__ attns)
{
    extern __shared__ __align__(16) char dsm[];
    const int bi = blockIdx.x, tid = threadIdx.x;
    const int lane = tid & 31, w = tid >> 5;
    int tgt = *(volatile int*)&g_bar_phase;

    for (int t = 0; t < 64; t++) {
        // ---- P1: LSTM0 GEMM: mtile=bi>>2 (32), ks=bi&3 (4), Kchunk=512 ----
        gemm_tile(g_Wc0_h, g_Wc0_l, g_Z0h, g_Z0l, 2048,
                  g_part + (size_t)(bi & 3) * 262144, 2048,
                  (bi >> 2) * 128, (bi & 3) * 512, 8, dsm);
        gsync(tgt);
        // ---- P2: cell0 ----
        cell_phase(bi * 512 + tid, g_part, g_embW + (size_t)t * 262144, g_bias0,
                   g_cT0, g_Z1h, g_Z1l, 0, g_Z0h, g_Z0l, 1024, nullptr);
        gsync(tgt);
        // ---- P3: LSTM1 GEMM ----
        gemm_tile(g_Wc1_h, g_Wc1_l, g_Z1h, g_Z1l, 2048,
                  g_part + (size_t)(bi & 3) * 262144, 2048,
                  (bi >> 2) * 128, (bi & 3) * 512, 8, dsm);
        gsync(tgt);
        // ---- P4: cell1 (also emits fp32 h1) ----
        cell_phase(bi * 512 + tid, g_part, nullptr, g_bias1,
                   g_cT1, g_Zoh, g_Zol, 1024, g_Z1h, g_Z1l, 1024, g_h1f);
        gsync(tgt);
        // ---- P5: CTAs 0-63 attention; CTAs 64-127 out-GEMM h1 half ----
        if (bi < 64) {
            const int b = bi;
            float* qs = (float*)dsm;          // 1024 fp32 h1[b]
            float* sc = qs + 1024;            // 64 scores
            for (int d = tid; d < 1024; d += 512) qs[d] = g_h1f[b * 1024 + d];
            __syncthreads();
            const int bpair = b >> 1, brow = (b & 1) * 64;
#pragma unroll
            for (int so = 0; so < 4; so++) {
                int s = w * 4 + so;
                float acc = 0.f;
#pragma unroll
                for (int eblk = 0; eblk < 16; eblk++) {
                    const float* cwp = g_ctxWT +
                        ((size_t)(bpair * 16 + eblk) * 128 + brow + s) * 64;
                    acc += qs[eblk * 64 + lane] * cwp[lane];
                    acc += qs[eblk * 64 + 32 + lane] * cwp[32 + lane];
                }
#pragma unroll
                for (int off = 16; off; off >>= 1)
                    acc += __shfl_down_sync(0xffffffffu, acc, off);
                if (lane == 0) sc[s] = acc;
            }
            __syncthreads();
            if (tid < 32) {
                float v0 = sc[tid], v1 = sc[tid + 32];
                float m = fmaxf(v0, v1);
#pragma unroll
                for (int off = 16; off; off >>= 1)
                    m = fmaxf(m, __shfl_xor_sync(0xffffffffu, m, off));
                float e0 = expf(v0 - m), e1 = expf(v1 - m);
                float s = e0 + e1;
#pragma unroll
                for (int off = 16; off; off >>= 1)
                    s += __shfl_xor_sync(0xffffffffu, s, off);
                float inv = 1.f / s;
                float a0 = e0 * inv, a1 = e1 * inv;
                sc[tid] = a0; sc[tid + 32] = a1;
                float* at = attns + (size_t)t * 4096 + b * 64;
                __stcs(at + tid, a0);
                __stcs(at + tid + 32, a1);
            }
            __syncthreads();
            for (int d = tid; d < 1024; d += 512) {
                float acc = 0.f;
#pragma unroll 8
                for (int s = 0; s < 64; s++)
                    acc += sc[s] * ctx[((size_t)s * 64 + b) * 1024 + d];
                bf16 hh, hl;
                hilo(acc, hh, hl);
                g_Zoh[b * 2048 + d] = hh;
                g_Zol[b * 2048 + d] = hl;
            }
        } else {
            const int idx = bi - 64;                  // 0..63
            const int mt = idx >> 3, ks = idx & 7;    // 8 mtiles x 8 ksplits
            gemm_tile(g_Wout_h, g_Wout_l, g_Zoh, g_Zol, 2048,
                      g_part + (size_t)(16 + ks) * 65536, 2048,
                      mt * 128, 1024 + ks * 128, 2, dsm);
        }
        gsync(tgt);
        // ---- P6: out GEMM cvec half: mtile=bi>>4 (8), ks=bi&15 (16), 1 chunk ----
        gemm_tile(g_Wout_h, g_Wout_l, g_Zoh, g_Zol, 2048,
                  g_part + (size_t)(bi & 15) * 65536, 2048,
                  (bi >> 4) * 128, (bi & 15) * 64, 1, dsm);
        gsync(tgt);
        // ---- P7: reduce 24 slices + tanh + outputs + next input feed ----
        {
            int e = bi * 512 + tid;
            int d = e >> 6, b = e & 63;
            float acc = 0.f;
#pragma unroll
            for (int ks = 0; ks < 24; ks++)
                acc += __ldcs(g_part + (size_t)ks * 65536 + e);
            float h = tanhf(acc);
            __stcs(outs + (size_t)t * 65536 + b * 1024 + d, h);
            bf16 hh, hl;
            hilo(h, hh, hl);
            g_Z0h[b * 2048 + d] = hh;
            g_Z0l[b * 2048 + d] = hl;
        }
        gsync(tgt);
    }
}

// ---------------- embW precompute GEMM (standalone, 2048 CTAs) ----------------
__global__ void __launch_bounds__(512) gemm_pre(float* __restrict__ out)
{
    extern __shared__ __align__(16) char dsm[];
    gemm_tile(g_W0e_h, g_W0e_l,
              g_embh + (size_t)blockIdx.y * 65536, g_embl + (size_t)blockIdx.y * 65536,
              1024, out + (size_t)blockIdx.y * 262144, 1024,
              blockIdx.x * 128, 0, 16, dsm);
}

// ---------------- ctxW precompute ----------------
__global__ void __launch_bounds__(512) ctxw_pre(float* __restrict__ out)
{
    extern __shared__ __align__(16) char dsm[];
    const int bpair = blockIdx.x;   // 32
    const int eblk  = blockIdx.y;   // 16
    gemm_tile(g_ctxRh + (size_t)bpair * 131072, g_ctxRl + (size_t)bpair * 131072,
              g_WinT_h + (size_t)eblk * 65536, g_WinT_l + (size_t)eblk * 65536,
              1024, out + ((size_t)bpair * 16 + eblk) * 8192, 1024,
              0, 0, 16, dsm);
}

// ---------------- init state ----------------
__global__ void init_state(const float* __restrict__ input_feed,
                           const float* __restrict__ h0, const float* __restrict__ c0)
{
    int e = blockIdx.x * blockDim.x + threadIdx.x;  // 65536
    int b = e >> 10, d = e & 1023;
    bf16 hh, hl;
    hilo(input_feed[e], hh, hl);
    g_Z0h[b * 2048 + d] = hh; g_Z0l[b * 2048 + d] = hl;
    hilo(h0[e], hh, hl);
    g_Z0h[b * 2048 + 1024 + d] = hh; g_Z0l[b * 2048 + 1024 + d] = hl;
    hilo(h0[65536 + e], hh, hl);
    g_Z1h[b * 2048 + 1024 + d] = hh; g_Z1l[b * 2048 + 1024 + d] = hl;
    g_cT0[d * 64 + b] = c0[e];
    g_cT1[d * 64 + b] = c0[65536 + e];
}

// ---------------- weight prep ----------------
__global__ void prep_w(const float* __restrict__ W_ih0, const float* __restrict__ W_hh0,
                       const float* __restrict__ W_ih1, const float* __restrict__ W_hh1,
                       const float* __restrict__ W_in,  const float* __restrict__ W_out,
                       const float* __restrict__ emb,   const float* __restrict__ ctx,
                       const float* __restrict__ b_ih0, const float* __restrict__ b_hh0,
                       const float* __restrict__ b_ih1, const float* __restrict__ b_hh1)
{
    size_t stride = (size_t)gridDim.x * blockDim.x;
    for (size_t i = (size_t)blockIdx.x * blockDim.x + threadIdx.x;
         i < 4096ull * 2048ull; i += stride) {
        size_t n = i >> 11, k = i & 2047;
        float v0 = (k < 1024) ? W_ih0[n * 2048 + 1024 + k] : W_hh0[n * 1024 + (k - 1024)];
        hilo(v0, g_Wc0_h[i], g_Wc0_l[i]);
        float v1 = (k < 1024) ? W_ih1[n * 1024 + k] : W_hh1[n * 1024 + (k - 1024)];
        hilo(v1, g_Wc1_h[i], g_Wc1_l[i]);
        if (n < 1024) hilo(W_out[i], g_Wout_h[i], g_Wout_l[i]);
        if (i < 4096ull * 1024ull) {
            size_t nn = i >> 10, kk = i & 1023;
            hilo(W_ih0[nn * 2048 + kk], g_W0e_h[i], g_W0e_l[i]);
            hilo(emb[i], g_embh[i], g_embl[i]);
            size_t b = (i >> 10) & 63, s = i >> 16, d = i & 1023;
            size_t ri = ((b >> 1) * 128 + (b & 1) * 64 + s) * 1024 + d;
            hilo(ctx[i], g_ctxRh[ri], g_ctxRl[ri]);
        }
        if (i < 1024ull * 1024ull) {
            size_t ti = (i & 1023) * 1024 + (i >> 10);
            hilo(W_in[i], g_WinT_h[ti], g_WinT_l[ti]);
        }
        if (i < 4096) {
            g_bias0[i] = b_ih0[i] + b_hh0[i];
            g_bias1[i] = b_ih1[i] + b_hh1[i];
        }
    }
}

// ---------------- host orchestration ----------------
extern "C" void kernel_launch(void* const* d_in, const int* in_sizes, int n_in,
                              void* d_out, int out_size)
{
    (void)in_sizes; (void)n_in; (void)out_size;
    const float* emb        = (const float*)d_in[0];
    const float* context    = (const float*)d_in[1];
    const float* input_feed = (const float*)d_in[2];
    const float* h0         = (const float*)d_in[3];
    const float* c0         = (const float*)d_in[4];
    const float* W_ih0      = (const float*)d_in[5];
    const float* W_hh0      = (const float*)d_in[6];
    const float* b_ih0      = (const float*)d_in[7];
    const float* b_hh0      = (const float*)d_in[8];
    const float* W_ih1      = (const float*)d_in[9];
    const float* W_hh1      = (const float*)d_in[10];
    const float* b_ih1      = (const float*)d_in[11];
    const float* b_hh1      = (const float*)d_in[12];
    const float* W_in       = (const float*)d_in[13];
    const float* W_out      = (const float*)d_in[14];

    float* outs  = (float*)d_out;
    float* attns = outs + 64 * 64 * 1024;

    static bool attr_set = false;
    if (!attr_set) {
        cudaFuncSetAttribute(persistent_k, cudaFuncAttributeMaxDynamicSharedMemorySize, GEMM_SMEM);
        cudaFuncSetAttribute(gemm_pre, cudaFuncAttributeMaxDynamicSharedMemorySize, GEMM_SMEM);
        cudaFuncSetAttribute(ctxw_pre, cudaFuncAttributeMaxDynamicSharedMemorySize, GEMM_SMEM);
        attr_set = true;
    }

    float *pEmbW, *pCtxWT;
    cudaGetSymbolAddress((void**)&pEmbW, g_embW);
    cudaGetSymbolAddress((void**)&pCtxWT, g_ctxWT);

    prep_w<<<4096, 256>>>(W_ih0, W_hh0, W_ih1, W_hh1, W_in, W_out, emb, context,
                          b_ih0, b_hh0, b_ih1, b_hh1);
    init_state<<<256, 256>>>(input_feed, h0, c0);
    ctxw_pre<<<dim3(32, 16), 512, GEMM_SMEM>>>(pCtxWT);
    gemm_pre<<<dim3(32, 64), 512, GEMM_SMEM>>>(pEmbW);
    persistent_k<<<NCTA, 512, GEMM_SMEM>>>(context, outs, attns);
}

// round 10
// speedup vs baseline: 1.4760x; 1.0264x over previous
#include <cuda_runtime.h>
#include <cuda_bf16.h>
#include <cstdint>
#include <math.h>

typedef __nv_bfloat16 bf16;

// Shapes: T=64, B=64, S=64, E=1024, D=1024, G=4096
// Persistent kernel: 128 CTAs x 512 threads, one CTA per SM, 6 fast global barriers/step.
// GEMM: out[n][b] split-K partials = sum_k W[n][k]*Z[b][k], 3-term hi/lo bf16 mma.sync.
// Attention: scores via ctxW precompute; output GEMM linearized via ctxOut precompute:
//   attn_h = tanh( sum_s align[s]*ctxOut[s,b,:] + Wout_h . h1 ).

#define NCTA 128

// ---------------- static device scratch ----------------
__device__ __align__(16) bf16 g_Wc0_h[4096*3072], g_Wc0_l[4096*3072];  // [W_ih0 | W_hh0]
__device__ __align__(16) bf16 g_Wc1_h[4096*2048], g_Wc1_l[4096*2048];  // [W_ih1 | W_hh1]
__device__ __align__(16) bf16 g_WinT_h[1024*1024], g_WinT_l[1024*1024];// W_in^T: [e][d]
__device__ __align__(16) bf16 g_Wout_h[1024*2048], g_Wout_l[1024*2048];
__device__ __align__(16) bf16 g_embh[4096*1024],  g_embl[4096*1024];   // emb rows (t*64+b)
__device__ __align__(16) bf16 g_ctxRh[4096*1024], g_ctxRl[4096*1024];  // ctx repacked per bpair
__device__ __align__(16) bf16 g_ctxPh[4096*1024], g_ctxPl[4096*1024];  // ctx plain [(s*64+b)][d]
__device__ __align__(16) float g_ctxWT[64*64*1024];  // [(bpair*16+eblk)][srow(128)][elocal(64)]
__device__ __align__(16) float g_ctxOut[1024*64*64]; // [(n*64+b)][s]
__device__ __align__(16) float g_part[24*1024*64];   // split-K partials
__device__ __align__(16) bf16 g_Z0h[64*2048], g_Z0l[64*2048];  // [feed | h0_prev]
__device__ __align__(16) bf16 g_Z1h[64*2048], g_Z1l[64*2048];  // [h0_new | h1_prev]
__device__ __align__(16) bf16 g_Zoh[64*2048], g_Zol[64*2048];  // [unused | h1_new]
__device__ __align__(16) float g_h1f[64*1024];                 // fp32 h1 [b][d]
__device__ __align__(16) float g_align[64*64];                 // align [b][s]
__device__ __align__(16) float g_cT0[1024*64], g_cT1[1024*64];
__device__ __align__(16) float g_bias0[4096], g_bias1[4096];
__device__ volatile int g_arrive[NCTA];
__device__ volatile int g_release;

// ---------------- PTX helpers ----------------
__device__ __forceinline__ uint32_t smem_u32(const void* p) {
    uint32_t a;
    asm("{ .reg .u64 t; cvta.to.shared.u64 t, %1; cvt.u32.u64 %0, t; }" : "=r"(a) : "l"(p));
    return a;
}
__device__ __forceinline__ void ldm4(uint32_t* r, uint32_t a) {
    asm volatile("ldmatrix.sync.aligned.m8n8.x4.shared.b16 {%0,%1,%2,%3}, [%4];"
                 : "=r"(r[0]), "=r"(r[1]), "=r"(r[2]), "=r"(r[3]) : "r"(a));
}
__device__ __forceinline__ void mma_bf16(float* c, const uint32_t* a, uint32_t b0, uint32_t b1) {
    asm volatile("mma.sync.aligned.m16n8k16.row.col.f32.bf16.bf16.f32 "
                 "{%0,%1,%2,%3}, {%4,%5,%6,%7}, {%8,%9}, {%0,%1,%2,%3};"
                 : "+f"(c[0]), "+f"(c[1]), "+f"(c[2]), "+f"(c[3])
                 : "r"(a[0]), "r"(a[1]), "r"(a[2]), "r"(a[3]), "r"(b0), "r"(b1));
}
__device__ __forceinline__ void cpa16(uint32_t s, const void* g) {
    asm volatile("cp.async.cg.shared.global [%0], [%1], 16;" :: "r"(s), "l"(g));
}
#define CP_COMMIT() asm volatile("cp.async.commit_group;" ::: "memory")

__device__ __forceinline__ void hilo(float x, bf16& h, bf16& l) {
    h = __float2bfloat16(x);
    l = __float2bfloat16(x - __bfloat162float(h));
}

// fast global barrier: per-CTA arrive flags (distinct addrs) + CTA0 scan + release word
__device__ __forceinline__ void gsync(int& tgt, int bi) {
    __syncthreads();
    tgt++;
    if (threadIdx.x == 0) { __threadfence(); g_arrive[bi] = tgt; }
    if (bi == 0) {
        if (threadIdx.x < NCTA) {
            while (g_arrive[threadIdx.x] - tgt < 0) {}
        }
        __syncthreads();
        if (threadIdx.x == 0) { __threadfence(); g_release = tgt; }
    } else {
        if (threadIdx.x == 0) {
            while (g_release - tgt < 0) {}
            __threadfence();
        }
    }
    __syncthreads();
}

// ---------------- GEMM tile (device fn; 512 threads, 4x4 warp grid) ----------------
// Dual Z source: k < kbound reads (Zh,Zl,ldz); k >= kbound reads (Z2h,Z2l,ldz2) at k-kbound.
// Output: out[(size_t)m*strideM + b*strideB]; strideB==1 uses vector evict-first stores.
static constexpr int PITCH = 72;
static constexpr int WBYTES = 128 * PITCH * 2;
static constexpr int ZBYTES = 64 * PITCH * 2;
static constexpr int BUFBYTES = 2 * WBYTES + 2 * ZBYTES;  // 55296
static constexpr int GEMM_SMEM = 2 * BUFBYTES;            // 110592

__device__ __forceinline__ void gemm_tile(
    const bf16* __restrict__ Wh, const bf16* __restrict__ Wl,
    const bf16* __restrict__ Zh, const bf16* __restrict__ Zl, int ldz,
    const bf16* __restrict__ Z2h, const bf16* __restrict__ Z2l, int ldz2, int kbound,
    float* __restrict__ out, size_t strideM, int strideB,
    int K, int n0, int k0, int chunks, char* dsm)
{
    const int tid  = threadIdx.x;
    const int lane = tid & 31, wid = tid >> 5;
    const int wm = wid >> 2, wn = wid & 3;
    const uint32_t sb = smem_u32(dsm);

    float acc[2][2][4];
#pragma unroll
    for (int mi = 0; mi < 2; mi++)
#pragma unroll
        for (int nj = 0; nj < 2; nj++)
#pragma unroll
            for (int q = 0; q < 4; q++) acc[mi][nj][q] = 0.f;

    auto stage = [&](int c) {
        const uint32_t S = sb + (c & 1) * BUFBYTES;
        const int kb = k0 + c * 64;
#pragma unroll
        for (int i = 0; i < 2; i++) {
            int idx = i * 512 + tid;
            int row = idx >> 3, cg = idx & 7;
            size_t g = (size_t)(n0 + row) * K + kb + cg * 8;
            uint32_t d = S + (row * PITCH + cg * 8) * 2;
            cpa16(d, Wh + g);
            cpa16(d + WBYTES, Wl + g);
        }
        {
            int row = tid >> 3, cg = tid & 7;
            const bf16 *zh, *zl; size_t g;
            if (kb < kbound) {
                g = (size_t)row * ldz + kb + cg * 8;
                zh = Zh; zl = Zl;
            } else {
                g = (size_t)row * ldz2 + (kb - kbound) + cg * 8;
                zh = Z2h; zl = Z2l;
            }
            uint32_t d = S + 2 * WBYTES + (row * PITCH + cg * 8) * 2;
            cpa16(d, zh + g);
            cpa16(d + ZBYTES, zl + g);
        }
        CP_COMMIT();
    };

    stage(0);
    for (int c = 0; c < chunks; c++) {
        if (c + 1 < chunks) {
            stage(c + 1);
            asm volatile("cp.async.wait_group 1;" ::: "memory");
        } else {
            asm volatile("cp.async.wait_group 0;" ::: "memory");
        }
        __syncthreads();

        const uint32_t S = sb + (c & 1) * BUFBYTES;
        const uint32_t aw = S + ((wm * 32 + (lane & 15)) * PITCH + (lane >> 4) * 8) * 2;
        const uint32_t bz = S + 2 * WBYTES + ((wn * 16 + (lane & 15)) * PITCH + (lane >> 4) * 8) * 2;

#pragma unroll
        for (int ks = 0; ks < 4; ks++) {
            const uint32_t koff = ks * 32;
            uint32_t ah[2][4], al[2][4], bh[4], bl[4];
#pragma unroll
            for (int mi = 0; mi < 2; mi++) {
                uint32_t a = aw + mi * 16 * PITCH * 2 + koff;
                ldm4(ah[mi], a);
                ldm4(al[mi], a + WBYTES);
            }
            ldm4(bh, bz + koff);
            ldm4(bl, bz + koff + ZBYTES);
#pragma unroll
            for (int mi = 0; mi < 2; mi++)
#pragma unroll
                for (int nj = 0; nj < 2; nj++) {
                    mma_bf16(acc[mi][nj], ah[mi], bh[nj], bh[2 + nj]);
                    mma_bf16(acc[mi][nj], ah[mi], bl[nj], bl[2 + nj]);
                    mma_bf16(acc[mi][nj], al[mi], bh[nj], bh[2 + nj]);
                }
        }
        __syncthreads();
    }

#pragma unroll
    for (int mi = 0; mi < 2; mi++)
#pragma unroll
        for (int nj = 0; nj < 2; nj++) {
            int m = n0 + wm * 32 + mi * 16 + (lane >> 2);
            int b = wn * 16 + nj * 8 + (lane & 3) * 2;
            if (strideB == 1) {
                __stcs((float2*)(out + (size_t)m * strideM + b),
                       make_float2(acc[mi][nj][0], acc[mi][nj][1]));
                __stcs((float2*)(out + (size_t)(m + 8) * strideM + b),
                       make_float2(acc[mi][nj][2], acc[mi][nj][3]));
            } else {
                out[(size_t)m * strideM + (size_t)b * strideB]           = acc[mi][nj][0];
                out[(size_t)m * strideM + (size_t)(b + 1) * strideB]     = acc[mi][nj][1];
                out[(size_t)(m + 8) * strideM + (size_t)b * strideB]     = acc[mi][nj][2];
                out[(size_t)(m + 8) * strideM + (size_t)(b + 1) * strideB] = acc[mi][nj][3];
            }
        }
}

// ---------------- cell phase (one element per thread; 128 CTAs) ----------------
__device__ __forceinline__ void cell_phase(
    int e, const float* __restrict__ part, const float* __restrict__ bias,
    float* __restrict__ cT,
    bf16* hAh, bf16* hAl, int offA, bf16* hBh, bf16* hBl, int offB,
    float* __restrict__ h1f)
{
    int d = e >> 6, b = e & 63;
    float g[4];
#pragma unroll
    for (int j = 0; j < 4; j++) {
        float acc = bias[j * 1024 + d];
#pragma unroll
        for (int ks = 0; ks < 4; ks++)
            acc += __ldcs(part + (size_t)ks * 262144 + (size_t)j * 65536 + e);
        g[j] = acc;
    }
    float ig = 1.f / (1.f + expf(-g[0]));
    float fg = 1.f / (1.f + expf(-g[1]));
    float gg = tanhf(g[2]);
    float og = 1.f / (1.f + expf(-g[3]));
    float cn = fg * cT[e] + ig * gg;
    float h  = og * tanhf(cn);
    cT[e] = cn;
    bf16 hh, hl;
    hilo(h, hh, hl);
    hAh[b * 2048 + offA + d] = hh; hAl[b * 2048 + offA + d] = hl;
    hBh[b * 2048 + offB + d] = hh; hBl[b * 2048 + offB + d] = hl;
    if (h1f) h1f[b * 1024 + d] = h;
}

// ---------------- persistent kernel ----------------
__global__ void __launch_bounds__(512) persistent_k(
    float* __restrict__ outs, float* __restrict__ attns)
{
    extern __shared__ __align__(16) char dsm[];
    const int bi = blockIdx.x, tid = threadIdx.x;
    const int lane = tid & 31, w = tid >> 5;
    int tgt = g_release;

    for (int t = 0; t < 64; t++) {
        // ---- P1: LSTM0 GEMM: K=3072 ([emb_t | feed | h0]); 32 mtiles x 4 ks ----
        gemm_tile(g_Wc0_h, g_Wc0_l,
                  g_embh + (size_t)t * 65536, g_embl + (size_t)t * 65536, 1024,
                  g_Z0h, g_Z0l, 2048, 1024,
                  g_part + (size_t)(bi & 3) * 262144, 64, 1,
                  3072, (bi >> 2) * 128, (bi & 3) * 768, 12, dsm);
        gsync(tgt, bi);
        // ---- P2: cell0 ----
        cell_phase(bi * 512 + tid, g_part, g_bias0,
                   g_cT0, g_Z1h, g_Z1l, 0, g_Z0h, g_Z0l, 1024, nullptr);
        gsync(tgt, bi);
        // ---- P3: LSTM1 GEMM ----
        gemm_tile(g_Wc1_h, g_Wc1_l, g_Z1h, g_Z1l, 2048,
                  g_Z1h, g_Z1l, 2048, 1 << 30,
                  g_part + (size_t)(bi & 3) * 262144, 64, 1,
                  2048, (bi >> 2) * 128, (bi & 3) * 512, 8, dsm);
        gsync(tgt, bi);
        // ---- P4: cell1 (also emits fp32 h1) ----
        cell_phase(bi * 512 + tid, g_part, g_bias1,
                   g_cT1, g_Zoh, g_Zol, 1024, g_Z1h, g_Z1l, 1024, g_h1f);
        gsync(tgt, bi);
        // ---- P5: CTAs 0-63 scores+softmax; CTAs 64-127 out-GEMM h1 half ----
        if (bi < 64) {
            const int b = bi;
            float* qs = (float*)dsm;          // 1024 fp32 h1[b]
            float* sc = qs + 1024;            // 64 scores
            for (int d = tid; d < 1024; d += 512) qs[d] = g_h1f[b * 1024 + d];
            __syncthreads();
            const int bpair = b >> 1, brow = (b & 1) * 64;
#pragma unroll
            for (int so = 0; so < 4; so++) {
                int s = w * 4 + so;
                float acc = 0.f;
#pragma unroll
                for (int eblk = 0; eblk < 16; eblk++) {
                    const float* cwp = g_ctxWT +
                        ((size_t)(bpair * 16 + eblk) * 128 + brow + s) * 64;
                    acc += qs[eblk * 64 + lane] * cwp[lane];
                    acc += qs[eblk * 64 + 32 + lane] * cwp[32 + lane];
                }
#pragma unroll
                for (int off = 16; off; off >>= 1)
                    acc += __shfl_down_sync(0xffffffffu, acc, off);
                if (lane == 0) sc[s] = acc;
            }
            __syncthreads();
            if (tid < 32) {
                float v0 = sc[tid], v1 = sc[tid + 32];
                float m = fmaxf(v0, v1);
#pragma unroll
                for (int off = 16; off; off >>= 1)
                    m = fmaxf(m, __shfl_xor_sync(0xffffffffu, m, off));
                float e0 = expf(v0 - m), e1 = expf(v1 - m);
                float s = e0 + e1;
#pragma unroll
                for (int off = 16; off; off >>= 1)
                    s += __shfl_xor_sync(0xffffffffu, s, off);
                float inv = 1.f / s;
                float a0 = e0 * inv, a1 = e1 * inv;
                g_align[b * 64 + tid] = a0;
                g_align[b * 64 + tid + 32] = a1;
                float* at = attns + (size_t)t * 4096 + b * 64;
                __stcs(at + tid, a0);
                __stcs(at + tid + 32, a1);
            }
        } else {
            const int idx = bi - 64;                  // 0..63
            const int mt = idx >> 3, ks = idx & 7;    // 8 mtiles x 8 ksplits
            gemm_tile(g_Wout_h, g_Wout_l, g_Zoh, g_Zol, 2048,
                      g_Zoh, g_Zol, 2048, 1 << 30,
                      g_part + (size_t)(16 + ks) * 65536, 64, 1,
                      2048, mt * 128, 1024 + ks * 128, 2, dsm);
        }
        gsync(tgt, bi);
        // ---- P6: combine: y = sum_s align*ctxOut + sum_ks part; tanh; outputs+feed ----
        {
            float* salign = (float*)dsm;   // 64*64
            for (int i = tid; i < 4096; i += 512) salign[i] = g_align[i];
            __syncthreads();
            int e = bi * 512 + tid;
            int n = e >> 6, b = e & 63;
            float acc = 0.f;
#pragma unroll
            for (int ks = 0; ks < 8; ks++)
                acc += __ldcs(g_part + (size_t)(16 + ks) * 65536 + e);
            const float4* co = (const float4*)(g_ctxOut + (size_t)e * 64);
            const float* al = salign + b * 64;
#pragma unroll
            for (int sq = 0; sq < 16; sq++) {
                float4 v = co[sq];
                acc += al[sq * 4 + 0] * v.x + al[sq * 4 + 1] * v.y
                     + al[sq * 4 + 2] * v.z + al[sq * 4 + 3] * v.w;
            }
            float h = tanhf(acc);
            __stcs(outs + (size_t)t * 65536 + b * 1024 + n, h);
            bf16 hh, hl;
            hilo(h, hh, hl);
            g_Z0h[b * 2048 + n] = hh;
            g_Z0l[b * 2048 + n] = hl;
        }
        gsync(tgt, bi);
    }
}

// ---------------- ctxW precompute: scores matrix ----------------
__global__ void __launch_bounds__(512) ctxw_pre(float* __restrict__ out)
{
    extern __shared__ __align__(16) char dsm[];
    const int bpair = blockIdx.x;   // 32
    const int eblk  = blockIdx.y;   // 16
    gemm_tile(g_ctxRh + (size_t)bpair * 131072, g_ctxRl + (size_t)bpair * 131072,
              g_WinT_h + (size_t)eblk * 65536, g_WinT_l + (size_t)eblk * 65536, 1024,
              g_WinT_h, g_WinT_l, 1024, 1 << 30,
              out + ((size_t)bpair * 16 + eblk) * 8192, 64, 1,
              1024, 0, 0, 16, dsm);
}

// ---------------- ctxOut precompute: [(n*64+b)][s] = Wout_c . ctx[s,b] ----------------
__global__ void __launch_bounds__(512) ctxout_pre(float* __restrict__ out)
{
    extern __shared__ __align__(16) char dsm[];
    const int mt = blockIdx.x;   // 8
    const int s  = blockIdx.y;   // 64
    gemm_tile(g_Wout_h, g_Wout_l,
              g_ctxPh + (size_t)s * 65536, g_ctxPl + (size_t)s * 65536, 1024,
              g_ctxPh, g_ctxPl, 1024, 1 << 30,
              out + s, 4096, 64,
              2048, mt * 128, 0, 16, dsm);
}

// ---------------- init state ----------------
__global__ void init_state(const float* __restrict__ input_feed,
                           const float* __restrict__ h0, const float* __restrict__ c0)
{
    int e = blockIdx.x * blockDim.x + threadIdx.x;  // 65536
    int b = e >> 10, d = e & 1023;
    bf16 hh, hl;
    hilo(input_feed[e], hh, hl);
    g_Z0h[b * 2048 + d] = hh; g_Z0l[b * 2048 + d] = hl;
    hilo(h0[e], hh, hl);
    g_Z0h[b * 2048 + 1024 + d] = hh; g_Z0l[b * 2048 + 1024 + d] = hl;
    hilo(h0[65536 + e], hh, hl);
    g_Z1h[b * 2048 + 1024 + d] = hh; g_Z1l[b * 2048 + 1024 + d] = hl;
    g_cT0[d * 64 + b] = c0[e];
    g_cT1[d * 64 + b] = c0[65536 + e];
    if (e == 0) g_release = g_release;  // no-op touch
}

// ---------------- weight prep ----------------
__global__ void prep_w(const float* __restrict__ W_ih0, const float* __restrict__ W_hh0,
                       const float* __restrict__ W_ih1, const float* __restrict__ W_hh1,
                       const float* __restrict__ W_in,  const float* __restrict__ W_out,
                       const float* __restrict__ emb,   const float* __restrict__ ctx,
                       const float* __restrict__ b_ih0, const float* __restrict__ b_hh0,
                       const float* __restrict__ b_ih1, const float* __restrict__ b_hh1)
{
    size_t stride = (size_t)gridDim.x * blockDim.x;
    for (size_t i = (size_t)blockIdx.x * blockDim.x + threadIdx.x;
         i < 4096ull * 3072ull; i += stride) {
        {   // Wc0: [W_ih0 (k<2048) | W_hh0]
            size_t n = i / 3072, k = i % 3072;
            float v = (k < 2048) ? W_ih0[n * 2048 + k] : W_hh0[n * 1024 + (k - 2048)];
            hilo(v, g_Wc0_h[i], g_Wc0_l[i]);
        }
        if (i < 4096ull * 2048ull) {
            size_t n = i >> 11, k = i & 2047;
            float v1 = (k < 1024) ? W_ih1[n * 1024 + k] : W_hh1[n * 1024 + (k - 1024)];
            hilo(v1, g_Wc1_h[i], g_Wc1_l[i]);
            if (n < 1024) hilo(W_out[i], g_Wout_h[i], g_Wout_l[i]);
        }
        if (i < 4096ull * 1024ull) {
            hilo(emb[i], g_embh[i], g_embl[i]);
            // ctx plain
            hilo(ctx[i], g_ctxPh[i], g_ctxPl[i]);
            // ctx re-pack: i = (s*64+b)*1024 + d -> row (b&1)*64+s of bpair b>>1
            size_t b = (i >> 10) & 63, s = i >> 16, d = i & 1023;
            size_t ri = ((b >> 1) * 128 + (b & 1) * 64 + s) * 1024 + d;
            hilo(ctx[i], g_ctxRh[ri], g_ctxRl[ri]);
        }
        if (i < 1024ull * 1024ull) {
            size_t ti = (i & 1023) * 1024 + (i >> 10);
            hilo(W_in[i], g_WinT_h[ti], g_WinT_l[ti]);
        }
        if (i < 4096) {
            g_bias0[i] = b_ih0[i] + b_hh0[i];
            g_bias1[i] = b_ih1[i] + b_hh1[i];
        }
    }
}

// ---------------- host orchestration ----------------
extern "C" void kernel_launch(void* const* d_in, const int* in_sizes, int n_in,
                              void* d_out, int out_size)
{
    (void)in_sizes; (void)n_in; (void)out_size;
    const float* emb        = (const float*)d_in[0];
    const float* context    = (const float*)d_in[1];
    const float* input_feed = (const float*)d_in[2];
    const float* h0         = (const float*)d_in[3];
    const float* c0         = (const float*)d_in[4];
    const float* W_ih0      = (const float*)d_in[5];
    const float* W_hh0      = (const float*)d_in[6];
    const float* b_ih0      = (const float*)d_in[7];
    const float* b_hh0      = (const float*)d_in[8];
    const float* W_ih1      = (const float*)d_in[9];
    const float* W_hh1      = (const float*)d_in[10];
    const float* b_ih1      = (const float*)d_in[11];
    const float* b_hh1      = (const float*)d_in[12];
    const float* W_in       = (const float*)d_in[13];
    const float* W_out      = (const float*)d_in[14];

    float* outs  = (float*)d_out;
    float* attns = outs + 64 * 64 * 1024;

    static bool attr_set = false;
    if (!attr_set) {
        cudaFuncSetAttribute(persistent_k, cudaFuncAttributeMaxDynamicSharedMemorySize, GEMM_SMEM);
        cudaFuncSetAttribute(ctxw_pre, cudaFuncAttributeMaxDynamicSharedMemorySize, GEMM_SMEM);
        cudaFuncSetAttribute(ctxout_pre, cudaFuncAttributeMaxDynamicSharedMemorySize, GEMM_SMEM);
        attr_set = true;
    }

    float *pCtxWT, *pCtxOut;
    cudaGetSymbolAddress((void**)&pCtxWT, g_ctxWT);
    cudaGetSymbolAddress((void**)&pCtxOut, g_ctxOut);

    prep_w<<<4096, 256>>>(W_ih0, W_hh0, W_ih1, W_hh1, W_in, W_out, emb, context,
                          b_ih0, b_hh0, b_ih1, b_hh1);
    init_state<<<256, 256>>>(input_feed, h0, c0);
    ctxw_pre<<<dim3(32, 16), 512, GEMM_SMEM>>>(pCtxWT);
    ctxout_pre<<<dim3(8, 64), 512, GEMM_SMEM>>>(pCtxOut);
    persistent_k<<<NCTA, 512, GEMM_SMEM>>>(outs, attns);
}